// round 1
// baseline (speedup 1.0000x reference)
#include <cuda_runtime.h>

// ---------------------------------------------------------------------------
// AttentionShareLocal: Swin window attention.
//   B=2048 windows, N=49 tokens, C=256 (8 heads x 32), fp32.
//   S = (Q K^T) * d^-0.5 + bias[h]  (bias from 2->64->8 MLP over 169 rel pos)
//   P = softmax(S, axis=-1);  O = P V
// Strategy:
//   kernel 1: compute 169x8 bias table once into __device__ global.
//   kernel 2: one CTA per (window, 2 heads). q/k/v slices + S in smem.
//             Packed fma.rn.f32x2 for both GEMMs (2x fp32 FMA throughput).
// ---------------------------------------------------------------------------

#define GS        7
#define NPOS      169
#define NH        8
#define HPB       2          // heads per block
#define NTOK      49
#define DH        32
#define QKV_STR   36         // padded row stride (floats) for q/k/v tiles
#define S_STR     49         // odd stride -> conflict-free column walks
#define THREADS   160

__device__ float g_pos[NPOS * NH];

// ---------------- bias table kernel (trivial cost, once per launch) --------
__global__ void bias_kernel(const float* __restrict__ W1, const float* __restrict__ b1,
                            const float* __restrict__ W2, const float* __restrict__ b2) {
    int p = threadIdx.x;
    if (p >= NPOS) return;
    float bh = (float)(p / 13 - 6);
    float bw = (float)(p % 13 - 6);
    float acc[NH];
#pragma unroll
    for (int h = 0; h < NH; h++) acc[h] = b2[h];
    for (int k = 0; k < 64; k++) {
        float hv = fmaf(bh, W1[k], fmaf(bw, W1[64 + k], b1[k]));
        hv = fmaxf(hv, 0.0f);
#pragma unroll
        for (int h = 0; h < NH; h++) acc[h] = fmaf(hv, W2[k * NH + h], acc[h]);
    }
#pragma unroll
    for (int h = 0; h < NH; h++) g_pos[p * NH + h] = acc[h];
}

// ---------------- packed f32x2 helpers (PTX-only; ptxas won't auto-fuse) ---
typedef unsigned long long u64;

__device__ __forceinline__ void fma2(u64& d, u64 a, u64 b) {
    asm("fma.rn.f32x2 %0, %1, %2, %0;" : "+l"(d) : "l"(a), "l"(b));
}
__device__ __forceinline__ float2 unpack2(u64 x) {
    float2 r;
    asm("mov.b64 {%0, %1}, %2;" : "=f"(r.x), "=f"(r.y) : "l"(x));
    return r;
}
__device__ __forceinline__ u64 splat2(float s) {
    u64 r;
    asm("mov.b64 %0, {%1, %1};" : "=l"(r) : "f"(s));
    return r;
}

// ---------------- main fused attention kernel ------------------------------
__global__ __launch_bounds__(THREADS, 3)
void attn_kernel(const float* __restrict__ Q, const float* __restrict__ K,
                 const float* __restrict__ V, float* __restrict__ O) {
    extern __shared__ float sm[];
    float* sQ   = sm;                                   // HPB*49*36
    float* sK   = sQ  + HPB * NTOK * QKV_STR;
    float* sV   = sK  + HPB * NTOK * QKV_STR;
    float* sS   = sV  + HPB * NTOK * QKV_STR;           // HPB*49*49
    float* sPos = sS  + HPB * NTOK * S_STR;             // HPB*169
    float* sInv = sPos + HPB * NPOS;                    // HPB*49

    const int t  = threadIdx.x;
    const int b  = blockIdx.x >> 2;
    const int hb = blockIdx.x & 3;                      // head-pair index 0..3

    const long gbase = (long)b * (NTOK * 256) + hb * (HPB * DH);

    // -------- Phase 1: stage q/k/v head slices (49 x 64 each) + pos table --
    // 784 float4 per tensor, fully coalesced (16 consecutive float4 per row).
    for (int idx = t; idx < 3 * 784; idx += THREADS) {
        int tsel = idx / 784;
        int rem  = idx - tsel * 784;
        int r    = rem >> 4;
        int c4   = rem & 15;
        const float* src = (tsel == 0 ? Q : (tsel == 1 ? K : V)) + gbase + r * 256 + c4 * 4;
        float4 val = *(const float4*)src;
        int hh = c4 >> 3;                 // which of the 2 heads
        int kk = (c4 & 7) * 4;            // 0..28
        float* dst = (tsel == 0 ? sQ : (tsel == 1 ? sK : sV))
                     + (hh * NTOK + r) * QKV_STR + kk;
        *(float4*)dst = val;
    }
    for (int idx = t; idx < HPB * NPOS; idx += THREADS) {
        int hh = idx / NPOS, p = idx - hh * NPOS;
        sPos[hh * NPOS + p] = g_pos[p * NH + hb * HPB + hh];
    }
    __syncthreads();

    // -------- Phase 2: S = QK^T * scale + bias  (7i x 5j register tiles) ---
    // 140 work items: h in {0,1}, igrp 0..6, jgrp 0..9
    if (t < HPB * 70) {
        int h    = t / 70;
        int it   = t - h * 70;
        int igrp = it / 10;
        int jgrp = it - igrp * 10;
        int i0 = igrp * 7;
        int j0 = jgrp * 5;

        const float* qh = sQ + (h * NTOK + i0) * QKV_STR;
        const float* kh = sK + h * NTOK * QKV_STR;
        const float* kp0[5];
#pragma unroll
        for (int w = 0; w < 5; w++) {
            int j = j0 + w; if (j > 48) j = 48;          // clamp (guarded at write)
            kp0[w] = kh + j * QKV_STR;
        }

        u64 acc[7][5];
#pragma unroll
        for (int u = 0; u < 7; u++)
#pragma unroll
            for (int w = 0; w < 5; w++) acc[u][w] = 0ull;

#pragma unroll 4
        for (int kpp = 0; kpp < 16; kpp++) {
            u64 q2[7], k2[5];
#pragma unroll
            for (int u = 0; u < 7; u++) q2[u] = *(const u64*)(qh + u * QKV_STR + kpp * 2);
#pragma unroll
            for (int w = 0; w < 5; w++) k2[w] = *(const u64*)(kp0[w] + kpp * 2);
#pragma unroll
            for (int u = 0; u < 7; u++)
#pragma unroll
                for (int w = 0; w < 5; w++) fma2(acc[u][w], q2[u], k2[w]);
        }

        const float scale = 0.17677669529663687f;   // 32^-0.5
        float* srow = sS + h * NTOK * S_STR;
        const float* ph = sPos + h * NPOS;
#pragma unroll
        for (int u = 0; u < 7; u++) {
            int i  = i0 + u;
            int fi = i + 6 * igrp;                  // i + 6*(i/7)
#pragma unroll
            for (int w = 0; w < 5; w++) {
                int j = j0 + w;
                if (j < NTOK) {
                    int fj = j + 6 * (j / 7);
                    float2 a = unpack2(acc[u][w]);
                    srow[i * S_STR + j] = (a.x + a.y) * scale + ph[fi - fj + 84];
                }
            }
        }
    }
    __syncthreads();

    // -------- Phase 3: softmax rows (thread per row; 1/sum deferred) -------
    if (t < HPB * NTOK) {
        int h = t / NTOK, i = t - h * NTOK;
        float* row = sS + (h * NTOK + i) * S_STR;
        float m = row[0];
#pragma unroll 7
        for (int j = 1; j < NTOK; j++) m = fmaxf(m, row[j]);
        float sum = 0.0f;
#pragma unroll 7
        for (int j = 0; j < NTOK; j++) {
            float e = exp2f((row[j] - m) * 1.4426950408889634f);
            row[j] = e;
            sum += e;
        }
        sInv[h * NTOK + i] = __frcp_rn(sum);
    }
    __syncthreads();

    // -------- Phase 4: O = P V  (7i x 4jj register tiles, splat f32x2) -----
    // 112 work items: h in {0,1}, igrp 0..6, jjgrp 0..7 (4 output cols each)
    if (t < HPB * 56) {
        int h     = t / 56;
        int r     = t - h * 56;
        int igrp  = r >> 3;
        int jjgrp = r & 7;
        int i0  = igrp * 7;
        int jj0 = jjgrp * 4;

        const float* Sp = sS + (h * NTOK + i0) * S_STR;
        const float* vp = sV + h * NTOK * QKV_STR + jj0;

        u64 acc0[7], acc1[7];
#pragma unroll
        for (int u = 0; u < 7; u++) { acc0[u] = 0ull; acc1[u] = 0ull; }

#pragma unroll 7
        for (int j = 0; j < NTOK; j++) {
            u64 va = *(const u64*)(vp + j * QKV_STR);
            u64 vb = *(const u64*)(vp + j * QKV_STR + 2);
#pragma unroll
            for (int u = 0; u < 7; u++) {
                u64 sp = splat2(Sp[u * S_STR + j]);
                fma2(acc0[u], sp, va);
                fma2(acc1[u], sp, vb);
            }
        }

        float* outp = O + (long)b * (NTOK * 256) + hb * (HPB * DH) + h * DH + jj0;
#pragma unroll
        for (int u = 0; u < 7; u++) {
            float inv = sInv[h * NTOK + i0 + u];
            float2 a = unpack2(acc0[u]);
            float2 c = unpack2(acc1[u]);
            float4 o;
            o.x = a.x * inv; o.y = a.y * inv; o.z = c.x * inv; o.w = c.y * inv;
            *(float4*)(outp + (i0 + u) * 256) = o;
        }
    }
}

// ---------------------------------------------------------------------------
extern "C" void kernel_launch(void* const* d_in, const int* in_sizes, int n_in,
                              void* d_out, int out_size) {
    const float* q  = (const float*)d_in[0];
    const float* k  = (const float*)d_in[1];
    const float* v  = (const float*)d_in[2];
    const float* W1 = (const float*)d_in[3];
    const float* b1 = (const float*)d_in[4];
    const float* W2 = (const float*)d_in[5];
    const float* b2 = (const float*)d_in[6];
    float* out = (float*)d_out;

    int B = in_sizes[0] / (NTOK * 256);

    const int smem_bytes = (3 * HPB * NTOK * QKV_STR   // q,k,v tiles
                            + HPB * NTOK * S_STR       // S
                            + HPB * NPOS               // pos slice
                            + HPB * NTOK)              // 1/sum
                           * (int)sizeof(float);

    cudaFuncSetAttribute(attn_kernel, cudaFuncAttributeMaxDynamicSharedMemorySize, smem_bytes);

    bias_kernel<<<1, 192>>>(W1, b1, W2, b2);
    attn_kernel<<<B * (NH / HPB), THREADS, smem_bytes>>>(q, k, v, out);
}